// round 4
// baseline (speedup 1.0000x reference)
#include <cuda_runtime.h>
#include <math.h>

#define H    2048
#define TPB  256            // 8 warps
#define NBLK 296            // 2 blocks per SM on 148 SMs, all co-resident
#define L    3

// Inter-layer hidden state ping-pong
__device__ __align__(16) float g_hbuf[2][H];

// Work-stealing counters (one per layer) — reset in-kernel so every graph
// replay starts from identical state.
__device__ unsigned g_ctr[L] = {0u, 0u, 0u};

// Sense-reversal grid barrier state. Two barriers per launch => g_sense and
// g_count return to 0 by kernel end (replay-safe).
__device__ volatile unsigned g_count = 0;
__device__ volatile unsigned g_sense = 0;

__device__ __forceinline__ float dot4(float4 w, float4 v) {
    return w.x * v.x + w.y * v.y + w.z * v.z + w.w * v.w;
}

__device__ __forceinline__ float sigmoidf_(float v) {
    return 1.0f / (1.0f + __expf(-v));
}

// Grid-wide barrier; the releasing (last-arriving) block also resets the
// work counter of the layer just completed, for the next replay.
__device__ __forceinline__ void grid_barrier(unsigned* local_sense, int layer_done) {
    __syncthreads();
    if (threadIdx.x == 0) {
        unsigned s = *local_sense ^ 1u;
        __threadfence();  // make this block's hout writes visible
        unsigned prev = atomicAdd((unsigned*)&g_count, 1u);
        if (prev == NBLK - 1) {
            g_ctr[layer_done] = 0u;   // reset consumed counter for next replay
            g_count = 0;
            __threadfence();
            g_sense = s;
        } else {
            while (g_sense != s) { __nanosleep(64); }
            __threadfence();          // acquire: see other blocks' writes
        }
        *local_sense = s;
    }
    __syncthreads();
}

__global__ void __launch_bounds__(TPB, 2) lstm_fused_kernel(
    const float* __restrict__ x,     // [H]
    const float* __restrict__ W_ih,  // [L, 4H, H]
    const float* __restrict__ W_hh,  // [L, 4H, H]
    const float* __restrict__ b_ih,  // [L, 4H]
    const float* __restrict__ b_hh,  // [L, 4H]
    const float* __restrict__ h0,    // [L, H]
    const float* __restrict__ c0,    // [L, H]
    float* __restrict__ out)         // [H]
{
    const int t    = threadIdx.x;
    const int warp = t >> 5;
    const int lane = t & 31;

    unsigned local_sense = 0;

    __shared__ int   sj;
    __shared__ float s[4][TPB / 32];

    #pragma unroll 1
    for (int layer = 0; layer < L; ++layer) {
        const float* xin  = (layer == 0) ? x : g_hbuf[layer - 1];
        const float* hin  = h0 + layer * H;
        const float* cin  = c0 + layer * H;
        float*       hout = (layer == 2) ? out : g_hbuf[layer];
        const float* Wi   = W_ih + (size_t)layer * 4 * H * H;
        const float* Wh   = W_hh + (size_t)layer * 4 * H * H;
        const float* bi   = b_ih + layer * 4 * H;
        const float* bh   = b_hh + layer * 4 * H;

        // Hoist this thread's slice of x and h into registers: the slice is
        // identical for every j this block processes in this layer.
        const float4* __restrict__ x4 = (const float4*)xin;
        const float4* __restrict__ h4 = (const float4*)hin;
        const float4 xv0 = x4[t];
        const float4 xv1 = x4[t + TPB];
        const float4 hv0 = h4[t];
        const float4 hv1 = h4[t + TPB];

        int last_fetch;
        #pragma unroll 1
        while (true) {
            if (t == 0) sj = (int)atomicAdd(&g_ctr[layer], 1u);
            __syncthreads();
            const int j = sj;
            if (j >= H) { last_fetch = j; break; }

            const float4* __restrict__ wi0 = (const float4*)(Wi + ((size_t)(0 * H + j)) * H);
            const float4* __restrict__ wi1 = (const float4*)(Wi + ((size_t)(1 * H + j)) * H);
            const float4* __restrict__ wi2 = (const float4*)(Wi + ((size_t)(2 * H + j)) * H);
            const float4* __restrict__ wi3 = (const float4*)(Wi + ((size_t)(3 * H + j)) * H);
            const float4* __restrict__ wh0 = (const float4*)(Wh + ((size_t)(0 * H + j)) * H);
            const float4* __restrict__ wh1 = (const float4*)(Wh + ((size_t)(1 * H + j)) * H);
            const float4* __restrict__ wh2 = (const float4*)(Wh + ((size_t)(2 * H + j)) * H);
            const float4* __restrict__ wh3 = (const float4*)(Wh + ((size_t)(3 * H + j)) * H);

            // Chunk A (k = t) and chunk B (k = t + 256): 16 independent
            // LDG.128 weight loads, FMAs against register-resident vectors.
            float4 pa0 = wi0[t];        float4 pa1 = wi1[t];
            float4 pa2 = wi2[t];        float4 pa3 = wi3[t];
            float4 qa0 = wh0[t];        float4 qa1 = wh1[t];
            float4 qa2 = wh2[t];        float4 qa3 = wh3[t];
            float4 pb0 = wi0[t + TPB];  float4 pb1 = wi1[t + TPB];
            float4 pb2 = wi2[t + TPB];  float4 pb3 = wi3[t + TPB];
            float4 qb0 = wh0[t + TPB];  float4 qb1 = wh1[t + TPB];
            float4 qb2 = wh2[t + TPB];  float4 qb3 = wh3[t + TPB];

            float a0 = dot4(pa0, xv0) + dot4(qa0, hv0) + dot4(pb0, xv1) + dot4(qb0, hv1);
            float a1 = dot4(pa1, xv0) + dot4(qa1, hv0) + dot4(pb1, xv1) + dot4(qb1, hv1);
            float a2 = dot4(pa2, xv0) + dot4(qa2, hv0) + dot4(pb2, xv1) + dot4(qb2, hv1);
            float a3 = dot4(pa3, xv0) + dot4(qa3, hv0) + dot4(pb3, xv1) + dot4(qb3, hv1);

            // Warp reduce 4 accumulators
            #pragma unroll
            for (int off = 16; off > 0; off >>= 1) {
                a0 += __shfl_xor_sync(0xffffffffu, a0, off);
                a1 += __shfl_xor_sync(0xffffffffu, a1, off);
                a2 += __shfl_xor_sync(0xffffffffu, a2, off);
                a3 += __shfl_xor_sync(0xffffffffu, a3, off);
            }
            if (lane == 0) {
                s[0][warp] = a0;
                s[1][warp] = a1;
                s[2][warp] = a2;
                s[3][warp] = a3;
            }
            __syncthreads();

            if (t == 0) {
                float gi = 0.f, gf = 0.f, gg = 0.f, go = 0.f;
                #pragma unroll
                for (int w = 0; w < TPB / 32; w++) {
                    gi += s[0][w]; gf += s[1][w];
                    gg += s[2][w]; go += s[3][w];
                }
                gi += bi[0 * H + j] + bh[0 * H + j];
                gf += bi[1 * H + j] + bh[1 * H + j];
                gg += bi[2 * H + j] + bh[2 * H + j];
                go += bi[3 * H + j] + bh[3 * H + j];

                float iv = sigmoidf_(gi);
                float fv = sigmoidf_(gf);
                float gv = tanhf(gg);
                float ov = sigmoidf_(go);
                float c_new = fv * cin[j] + iv * gv;
                hout[j] = ov * tanhf(c_new);
            }
            __syncthreads();  // protect s[][] and sj before next iteration
        }

        if (layer < L - 1) {
            grid_barrier(&local_sense, layer);
        } else {
            // Reset layer-2 counter: the block whose overflow fetch was the
            // very last one (value H + NBLK - 1) resets it for the next replay.
            if (t == 0 && last_fetch == H + NBLK - 1) {
                g_ctr[L - 1] = 0u;
            }
        }
    }
}

extern "C" void kernel_launch(void* const* d_in, const int* in_sizes, int n_in,
                              void* d_out, int out_size) {
    (void)in_sizes; (void)n_in; (void)out_size;
    const float* x    = (const float*)d_in[0];
    const float* W_ih = (const float*)d_in[1];
    const float* W_hh = (const float*)d_in[2];
    const float* b_ih = (const float*)d_in[3];
    const float* b_hh = (const float*)d_in[4];
    const float* h0   = (const float*)d_in[5];
    const float* c0   = (const float*)d_in[6];
    float* out = (float*)d_out;

    lstm_fused_kernel<<<NBLK, TPB>>>(x, W_ih, W_hh, b_ih, b_hh, h0, c0, out);
}